// round 10
// baseline (speedup 1.0000x reference)
#include <cuda_runtime.h>
#include <cuda_fp16.h>
#include <stdint.h>

// ============================================================
// Conv 3x3 pad=1 as fp16 implicit GEMM on HMMA, A-union tiling.
// R10: prep_x eliminated — conv_hmma converts its own A window from
// fp32 x directly into smem (coalesced 128B row loads + STS.u16 into
// pre-zeroed A buffers). Chunk0 in prologue, chunk1 spread over units
// 0..7. Only a tiny weight-transpose prep kernel remains.
// ============================================================

#define NPLANE 1156

__device__ __align__(256) __half g_wh[9 * 128 * 128];

__device__ __forceinline__ uint32_t smem_u32(const void* p) {
    uint32_t a;
    asm("{ .reg .u64 t; cvta.to.shared.u64 t, %1; cvt.u32.u64 %0, t; }" : "=r"(a) : "l"(p));
    return a;
}

#define CP_ASYNC16(dst, src, sz) \
    asm volatile("cp.async.cg.shared.global [%0], [%1], 16, %2;" :: "r"(dst), "l"(src), "r"(sz) : "memory")

__device__ __forceinline__ void ldm_x4(uint32_t* r, uint32_t addr) {
    asm volatile("ldmatrix.sync.aligned.m8n8.x4.shared.b16 {%0,%1,%2,%3}, [%4];"
                 : "=r"(r[0]), "=r"(r[1]), "=r"(r[2]), "=r"(r[3]) : "r"(addr));
}

__device__ __forceinline__ void mma_f16(float* c, const uint32_t* a, const uint32_t* b) {
    asm volatile(
        "mma.sync.aligned.m16n8k16.row.col.f32.f16.f16.f32 "
        "{%0,%1,%2,%3}, {%4,%5,%6,%7}, {%8,%9}, {%0,%1,%2,%3};"
        : "+f"(c[0]), "+f"(c[1]), "+f"(c[2]), "+f"(c[3])
        : "r"(a[0]), "r"(a[1]), "r"(a[2]), "r"(a[3]), "r"(b[0]), "r"(b[1]));
}

// ---------------- weight prep (tiny) ----------------
// 32 blocks x 256 thr: g_wh[(q*128 + f)*128 + c] = f16(w[f][c][q])

__global__ void prep_w(const float* __restrict__ w) {
    const int b = blockIdx.x, t = threadIdx.x;
    #pragma unroll
    for (int r = 0; r < 2; ++r) {
        int id = b * 512 + r * 256 + t;
        int f = id >> 7, c = id & 127;
        const float* wp = w + (size_t)(f * 128 + c) * 9;
        #pragma unroll
        for (int q = 0; q < 9; ++q)
            g_wh[(q * 128 + f) * 128 + c] = __float2half(wp[q]);
    }
}

// ---------------- main kernel ----------------
// 288 CTAs x 256 thr (8 warps, 2Mx4N, warp tile 64x32). CTA tile 128x128.
// SMEM rows 144B: A-union 2 x [198][144] @0; B ring 2 x [128][144] @57024.
// A filled in-kernel from fp32 x: zero-fill, then per (c, plane-row) one
// coalesced 128B load; lane w stores f16 at p = pr*34 + 1 + w - m0.

#define ROWB 144
#define A_STAGE 28512
#define B_BASE 57024
#define B_STAGE 18432
#define SMEM_DYN 93888
#define NUNITS 18
#define EPSTRIDE 18

__global__ __launch_bounds__(256, 2)
void conv_hmma(const float* __restrict__ x,
               const float* __restrict__ bias, float* __restrict__ out) {
    extern __shared__ char dynsmem[];
    __shared__ float bias_s[128];

    const int tid = threadIdx.x, wid = tid >> 5, lane = tid & 31;
    const int wm = wid >> 2, wn = wid & 3;
    const int T = blockIdx.x;
    const int n = T / 9, m0 = (T % 9) * 128;
    const int pr_lo = m0 / 34;

    if (tid < 128) bias_s[tid] = bias[tid];

    const uint32_t sd = smem_u32(dynsmem);
    const float* xn = x + (size_t)n * 128 * 1024;

    auto load_B = [&](int u) {
        const int q = u % 9, chunk = u / 9, c0 = chunk * 64;
        const uint32_t bbase = sd + B_BASE + (u & 1) * B_STAGE;
        #pragma unroll
        for (int it = 0; it < 4; ++it) {
            int idx = it * 256 + tid;
            int row = idx >> 3, ch = idx & 7;
            CP_ASYNC16(bbase + row * ROWB + ch * 16,
                       g_wh + (size_t)((q * 128 + row) * 128) + c0 + ch * 8, 16);
        }
        asm volatile("cp.async.commit_group;" ::: "memory");
    };

    // convert warp-tasks [t0, t1) of chunk: task t -> c = c0 + t/7, pr = pr_lo + t%7
    auto convert_A = [&](int chunk, int t0, int t1) {
        const int c0 = chunk * 64;
        char* abase = dynsmem + chunk * A_STAGE;
        for (int t = t0 + wid; t < t1; t += 8) {
            int cl = t / 7, ri = t - cl * 7;
            int pr = pr_lo + ri;
            int h = pr - 1;
            if ((unsigned)h < 32u) {
                int p = pr * 34 + 1 + lane - m0;
                if ((unsigned)p < 198u) {
                    float v = xn[(size_t)(c0 + cl) * 1024 + h * 32 + lane];
                    *(__half*)(abase + p * ROWB + cl * 2) = __float2half(v);
                }
            }
        }
    };

    // ---- prologue ----
    load_B(0);
    load_B(1);
    {   // zero both A chunks
        uint4 z = make_uint4(0, 0, 0, 0);
        #pragma unroll
        for (int it = 0; it < 14; ++it) {
            int idx = it * 256 + tid;
            if (idx < 2 * A_STAGE / 16) *(uint4*)(dynsmem + idx * 16) = z;
        }
    }
    __syncthreads();
    convert_A(0, 0, 448);

    float acc[4][4][4];
    #pragma unroll
    for (int i = 0; i < 4; ++i)
        #pragma unroll
        for (int j = 0; j < 4; ++j)
            #pragma unroll
            for (int r = 0; r < 4; ++r) acc[i][j][r] = 0.0f;

    const uint32_t a_lrow = (uint32_t)(wm * 64 + (lane & 15)) * ROWB + ((lane >> 4) << 4);
    const uint32_t b_lrow = (uint32_t)(wn * 32 + ((lane >> 4) << 3) + (lane & 7)) * ROWB
                            + ((lane & 8) ? 16u : 0u);

    for (int u = 0; u < NUNITS; ++u) {
        asm volatile("cp.async.wait_group 0;" ::: "memory");
        __syncthreads();   // B(u) visible, A converts visible, all warps past u-1
        if (u >= 1 && u + 1 < NUNITS) load_B(u + 1);

        const int q = u % 9, chunk = u / 9;
        const int shift = (q / 3) * 34 + (q % 3);
        const uint32_t abase = sd + chunk * A_STAGE + (uint32_t)shift * ROWB + a_lrow;
        const uint32_t bbase = sd + B_BASE + (u & 1) * B_STAGE + b_lrow;

        #pragma unroll
        for (int ks = 0; ks < 4; ++ks) {
            uint32_t Ah[16], Bh[8];
            const uint32_t ao = abase + ks * 32;
            #pragma unroll
            for (int i = 0; i < 4; ++i) ldm_x4(&Ah[4 * i], ao + i * 16 * ROWB);
            const uint32_t bo = bbase + ks * 32;
            ldm_x4(&Bh[0], bo);
            ldm_x4(&Bh[4], bo + 16 * ROWB);

            #pragma unroll
            for (int i = 0; i < 4; ++i)
                #pragma unroll
                for (int j = 0; j < 4; ++j)
                    mma_f16(acc[i][j], &Ah[4 * i], &Bh[(j >> 1) * 4 + (j & 1) * 2]);
        }

        // spread chunk1 conversion over units 0..7 (ready before unit 9)
        if (u < 8) convert_A(1, u * 56, u * 56 + 56);
    }

    __syncthreads();

    // ---------------- epilogue: 2 f-chunks of 16 via smem ----------------
    float* eps = (float*)dynsmem + wid * (64 * EPSTRIDE);
    const int g = lane >> 2, tg = lane & 3;
    const int mwbase = m0 + wm * 64;
    float* outn = out + (size_t)n * 128 * 1024;

    #pragma unroll
    for (int cj = 0; cj < 2; ++cj) {
        __syncwarp();
        #pragma unroll
        for (int i = 0; i < 4; ++i)
            #pragma unroll
            for (int jj = 0; jj < 2; ++jj) {
                int j = cj * 2 + jj;
                float* p0 = &eps[(i * 16 + g) * EPSTRIDE + jj * 8 + 2 * tg];
                float* p1 = &eps[(i * 16 + g + 8) * EPSTRIDE + jj * 8 + 2 * tg];
                *(float2*)p0 = make_float2(acc[i][j][0], acc[i][j][1]);
                *(float2*)p1 = make_float2(acc[i][j][2], acc[i][j][3]);
            }
        __syncwarp();

        #pragma unroll 1
        for (int f = 0; f < 16; ++f) {
            const int fg = wn * 32 + cj * 16 + f;
            const float bv = bias_s[fg];
            #pragma unroll
            for (int half = 0; half < 2; ++half) {
                int ml = half * 32 + lane;
                int m = mwbase + ml;
                int hh = m / 34, ww = m % 34;
                if (hh < 32 && ww < 32)
                    outn[(size_t)fg * 1024 + hh * 32 + ww] = eps[ml * EPSTRIDE + f] + bv;
            }
        }
    }
}

// ---------------- launch ----------------

extern "C" void kernel_launch(void* const* d_in, const int* in_sizes, int n_in,
                              void* d_out, int out_size) {
    const float* x = (const float*)d_in[0];
    const float* w = (const float*)d_in[1];
    const float* b = (const float*)d_in[2];
    float* out = (float*)d_out;

    cudaFuncSetAttribute(conv_hmma, cudaFuncAttributeMaxDynamicSharedMemorySize, SMEM_DYN);

    prep_w<<<32, 256>>>(w);
    conv_hmma<<<288, 256, SMEM_DYN>>>(x, b, out);
}